// round 7
// baseline (speedup 1.0000x reference)
#include <cuda_runtime.h>

#define D_IN   1024
#define D_OUT  1024
#define BATCH  32
#define E_TOT  3076              // D_OUT + 2*D_IN + 4
#define E_TAIL 2052              // E_TOT - D_OUT (rows needed in pass 1)
#define GROUP  8                 // batches per pipeline group (tail = 67 MB < L2)

// Scratch (device globals; no allocation allowed)
__device__ float g_out [BATCH * E_TAIL];   // w·x for rows [D_OUT, E)
__device__ float g_kphi[BATCH * D_IN];     // softmax(k)
__device__ float g_diff[BATCH * D_IN];     // softmax(q) - softmax(k)
__device__ float g_sigb[BATCH * 4];        // sigmoid(b1..b4)

// ---------------------------------------------------------------------------
// Kernel A: tail dots for one batch group.
// out[b, e] = dot(w[b, D_OUT+e, :], x[b, :]),  e in [0, E_TAIL)
// Normal-priority loads: this group's tail (67 MB) stays resident in L2
// for kernel C, which runs ~10us later with nothing in between to evict it.
// ---------------------------------------------------------------------------
__global__ void __launch_bounds__(256) kA_gemv(const float* __restrict__ x,
                                               const float* __restrict__ w,
                                               int b0)
{
    __shared__ float xs[D_IN];
    const int b   = b0 + blockIdx.y;
    const int tid = threadIdx.x;

    const float4* x4 = (const float4*)(x + (size_t)b * D_IN);
    for (int i = tid; i < D_IN / 4; i += 256)
        ((float4*)xs)[i] = x4[i];
    __syncthreads();

    const int warp = tid >> 5;
    const int lane = tid & 31;
    const int r = blockIdx.x * 8 + warp;
    if (r >= E_TAIL) return;

    const float4* wrow =
        (const float4*)(w + ((size_t)b * E_TOT + D_OUT + r) * (size_t)D_IN);

    float acc = 0.f;
#pragma unroll
    for (int i = 0; i < 8; i++) {
        float4 wv = __ldg(&wrow[i * 32 + lane]);       // keep resident in L2
        float4 xv = ((const float4*)xs)[i * 32 + lane];
        acc += wv.x * xv.x + wv.y * xv.y + wv.z * xv.z + wv.w * xv.w;
    }
#pragma unroll
    for (int o = 16; o; o >>= 1)
        acc += __shfl_xor_sync(0xFFFFFFFFu, acc, o);

    if (lane == 0)
        g_out[b * E_TAIL + r] = acc;
}

// ---------------------------------------------------------------------------
// Kernel B: per-batch softmax(k), softmax(q), diff = qphi - kphi, sigmoids.
// One block per batch in the group. Tiny; negligible L2 footprint.
// ---------------------------------------------------------------------------
__global__ void __launch_bounds__(256) kB_softmax(int b0)
{
    const int b   = b0 + blockIdx.x;
    const int tid = threadIdx.x;
    __shared__ float red[256];

    const float* ob = g_out + b * E_TAIL;

    // ---- k softmax ----
    float kv[4];
#pragma unroll
    for (int j = 0; j < 4; j++) kv[j] = ob[tid + j * 256];
    float m = fmaxf(fmaxf(kv[0], kv[1]), fmaxf(kv[2], kv[3]));
    red[tid] = m; __syncthreads();
    for (int s = 128; s; s >>= 1) {
        if (tid < s) red[tid] = fmaxf(red[tid], red[tid + s]);
        __syncthreads();
    }
    m = red[0]; __syncthreads();

    float sum = 0.f;
#pragma unroll
    for (int j = 0; j < 4; j++) { kv[j] = __expf(kv[j] - m); sum += kv[j]; }
    red[tid] = sum; __syncthreads();
    for (int s = 128; s; s >>= 1) {
        if (tid < s) red[tid] += red[tid + s];
        __syncthreads();
    }
    float inv = 1.f / red[0]; __syncthreads();
#pragma unroll
    for (int j = 0; j < 4; j++) {
        kv[j] *= inv;
        g_kphi[b * D_IN + tid + j * 256] = kv[j];
    }

    // ---- q softmax, diff ----
    float qv[4];
#pragma unroll
    for (int j = 0; j < 4; j++) qv[j] = ob[D_IN + tid + j * 256];
    m = fmaxf(fmaxf(qv[0], qv[1]), fmaxf(qv[2], qv[3]));
    red[tid] = m; __syncthreads();
    for (int s = 128; s; s >>= 1) {
        if (tid < s) red[tid] = fmaxf(red[tid], red[tid + s]);
        __syncthreads();
    }
    m = red[0]; __syncthreads();

    sum = 0.f;
#pragma unroll
    for (int j = 0; j < 4; j++) { qv[j] = __expf(qv[j] - m); sum += qv[j]; }
    red[tid] = sum; __syncthreads();
    for (int s = 128; s; s >>= 1) {
        if (tid < s) red[tid] += red[tid + s];
        __syncthreads();
    }
    inv = 1.f / red[0];
#pragma unroll
    for (int j = 0; j < 4; j++)
        g_diff[b * D_IN + tid + j * 256] = qv[j] * inv - kv[j];

    if (tid < 4)
        g_sigb[b * 4 + tid] = 1.f / (1.f + __expf(-ob[2 * D_IN + tid]));
}

// ---------------------------------------------------------------------------
// Kernel C: fused update for one batch group. Per row e of w:
//   dd = dot(w_row, diff); dx = dot(w_row, x)
//   w_out_row = w_row + sigmoid(beta[e]) * dd * kphi
// Rows processed tail-first (e descending) to consume the fresh L2 remnant
// kA just wrote. __ldcs reads (hit-or-stream, evict-first) and __stwt
// stores (no allocation) keep the remnant unpolluted.
// ---------------------------------------------------------------------------
__global__ void __launch_bounds__(256) kC_update(const float* __restrict__ x,
                                                 const float* __restrict__ w,
                                                 float* __restrict__ y,
                                                 float* __restrict__ wout,
                                                 int b0)
{
    __shared__ float xs[D_IN];
    __shared__ float ds[D_IN];
    __shared__ float ks[D_IN];
    const int b   = b0 + blockIdx.y;
    const int tid = threadIdx.x;

    for (int i = tid; i < D_IN / 4; i += 256) {
        ((float4*)xs)[i] = ((const float4*)(x      + (size_t)b * D_IN))[i];
        ((float4*)ds)[i] = ((const float4*)(g_diff + (size_t)b * D_IN))[i];
        ((float4*)ks)[i] = ((const float4*)(g_kphi + (size_t)b * D_IN))[i];
    }
    __syncthreads();

    const int warp = tid >> 5;
    const int lane = tid & 31;
    const int idx = blockIdx.x * 8 + warp;
    if (idx >= E_TOT) return;
    const int e = E_TOT - 1 - idx;                   // tail rows first (L2-hot)

    const size_t off = ((size_t)b * E_TOT + e) * (size_t)D_IN;
    const float4* wrow = (const float4*)(w    + off);
    float4*       orow = (float4*)      (wout + off);

    float4 wr[8];
    float dd = 0.f, dx = 0.f;
#pragma unroll
    for (int i = 0; i < 8; i++) {
        wr[i] = __ldcs(&wrow[i * 32 + lane]);        // L2 hit for tail rows
        float4 dv = ((const float4*)ds)[i * 32 + lane];
        float4 xv = ((const float4*)xs)[i * 32 + lane];
        dd += wr[i].x * dv.x + wr[i].y * dv.y + wr[i].z * dv.z + wr[i].w * dv.w;
        dx += wr[i].x * xv.x + wr[i].y * xv.y + wr[i].z * xv.z + wr[i].w * xv.w;
    }
#pragma unroll
    for (int o = 16; o; o >>= 1) {
        dd += __shfl_xor_sync(0xFFFFFFFFu, dd, o);
        dx += __shfl_xor_sync(0xFFFFFFFFu, dx, o);
    }

    // beta region: [0,1024)->b1, [1024,2048)->b2, [2048,3072)->b3, [3072,3076)->b4
    const int region = (e < 1024) ? 0 : (e < 2048) ? 1 : (e < 3072) ? 2 : 3;
    const float s = g_sigb[b * 4 + region] * dd;

#pragma unroll
    for (int i = 0; i < 8; i++) {
        float4 kv = ((const float4*)ks)[i * 32 + lane];
        float4 o;
        o.x = wr[i].x + s * kv.x;
        o.y = wr[i].y + s * kv.y;
        o.z = wr[i].z + s * kv.z;
        o.w = wr[i].w + s * kv.w;
        __stwt(&orow[i * 32 + lane], o);             // write-through, no L2 alloc
    }

    if (e < D_OUT && lane == 0)
        y[(size_t)b * D_OUT + e] = dx;
}

// ---------------------------------------------------------------------------
extern "C" void kernel_launch(void* const* d_in, const int* in_sizes, int n_in,
                              void* d_out, int out_size)
{
    const float* x = (const float*)d_in[0];   // (32, 1024)
    const float* w = (const float*)d_in[1];   // (32, 3076, 1024)
    float* y    = (float*)d_out;              // (32, 1024)
    float* wout = y + (size_t)BATCH * D_OUT;  // (32, 3076, 1024)

    const dim3 gA((E_TAIL + 7) / 8, GROUP);   // 257 x 8
    const dim3 gC((E_TOT  + 7) / 8, GROUP);   // 385 x 8

    for (int b0 = 0; b0 < BATCH; b0 += GROUP) {
        kA_gemv  <<<gA, 256>>>(x, w, b0);
        kB_softmax<<<GROUP, 256>>>(b0);
        kC_update<<<gC, 256>>>(x, w, y, wout, b0);
    }
}